// round 1
// baseline (speedup 1.0000x reference)
#include <cuda_runtime.h>
#include <cuda_bf16.h>
#include <math.h>

// ---------------------------------------------------------------------------
// SNN_CNN_Hybrid: T=16 steps of [conv1(5x5,s2,p2)+LIF, conv2(3x3,s2,p1)+LIF]
// then decoder conv(3x3,s1,p1)+relu -> convT(4x4,s2,p1)+relu -> convT(4x4,s2,p1)+softplus
// All fp32, deterministic accumulation order.
// ---------------------------------------------------------------------------

#define T_STEPS 16
#define BATCH   32
#define H0 100
#define W0 368
#define C1 16
#define H1 50
#define W1 184
#define C2 32
#define H2 25
#define W2 92
#define CD 64
#define H3 50
#define W3 184
#define H4 100
#define W4 368

#define M1_N (BATCH*C1*H1*W1)          // 4,710,400
#define M2_N (BATCH*C2*H2*W2)          // 2,355,200
#define H1_N (BATCH*CD*H2*W2)          // 4,710,400
#define H2_N (BATCH*C2*H3*W3)          // 9,420,800

// Persistent scratch (no allocations allowed)
__device__ float g_m1[M1_N];
__device__ float g_s1[M1_N];
__device__ float g_m2[M2_N];
__device__ float g_h1[H1_N];
__device__ float g_h2[H2_N];

// ---------------------------------------------------------------------------
// Kernel A: conv1 (1->16ch, 5x5, s2, p2) + LIF update of m1, emit s1
// thread = one (b, oy, ox); computes all 16 channels.
// ---------------------------------------------------------------------------
__global__ void k_conv1_lif(const float* __restrict__ x,
                            const float* __restrict__ w1,
                            float* __restrict__ m1,
                            float* __restrict__ s1,
                            int t)
{
    __shared__ __align__(16) float ws[25 * 16];   // [tap][oc]
    for (int i = threadIdx.x; i < 400; i += blockDim.x) {
        int oc = i & 15, tap = i >> 4;
        ws[i] = w1[oc * 25 + tap];
    }
    __syncthreads();

    int idx = blockIdx.x * blockDim.x + threadIdx.x;
    if (idx >= BATCH * H1 * W1) return;
    int ox = idx % W1;
    int tmp = idx / W1;
    int oy = tmp % H1;
    int b  = tmp / H1;

    float acc[16];
#pragma unroll
    for (int i = 0; i < 16; i++) acc[i] = 0.f;

    const float* xb = x + ((size_t)t * BATCH + b) * (H0 * W0);

#pragma unroll
    for (int ky = 0; ky < 5; ky++) {
        int iy = oy * 2 - 2 + ky;
        if ((unsigned)iy >= (unsigned)H0) continue;
        const float* xr = xb + iy * W0;
#pragma unroll
        for (int kx = 0; kx < 5; kx++) {
            int ix = ox * 2 - 2 + kx;
            if ((unsigned)ix >= (unsigned)W0) continue;
            float v = __ldg(xr + ix);
            const float4* wk = (const float4*)(ws + (ky * 5 + kx) * 16);
#pragma unroll
            for (int j = 0; j < 4; j++) {
                float4 w = wk[j];
                acc[4*j+0] = fmaf(v, w.x, acc[4*j+0]);
                acc[4*j+1] = fmaf(v, w.y, acc[4*j+1]);
                acc[4*j+2] = fmaf(v, w.z, acc[4*j+2]);
                acc[4*j+3] = fmaf(v, w.w, acc[4*j+3]);
            }
        }
    }

    size_t base = (size_t)b * C1 * H1 * W1 + (size_t)oy * W1 + ox;
#pragma unroll
    for (int oc = 0; oc < 16; oc++) {
        size_t o = base + (size_t)oc * (H1 * W1);
        float m = m1[o] * 0.5f + acc[oc];
        bool sp = (m >= 1.0f);
        m1[o] = sp ? 0.f : m;
        s1[o] = sp ? 1.f : 0.f;
    }
}

// ---------------------------------------------------------------------------
// Kernel B: conv2 (16->32ch, 3x3, s2, p1) over s1 + LIF update of m2
// thread = one (b, oy, ox); computes all 32 channels.
// ---------------------------------------------------------------------------
__global__ void k_conv2_lif(const float* __restrict__ s1,
                            const float* __restrict__ w2,
                            float* __restrict__ m2)
{
    __shared__ __align__(16) float ws[16 * 9 * 32];   // [(ic*9+kk)][oc]
    for (int i = threadIdx.x; i < 4608; i += blockDim.x) {
        // ws[i] where i = r*32 + oc ; src w2[oc*144 + r]
        int oc = i & 31, r = i >> 5;
        ws[i] = w2[oc * 144 + r];
    }
    __syncthreads();

    int idx = blockIdx.x * blockDim.x + threadIdx.x;
    if (idx >= BATCH * H2 * W2) return;
    int ox = idx % W2;
    int tmp = idx / W2;
    int oy = tmp % H2;
    int b  = tmp / H2;

    float acc[32];
#pragma unroll
    for (int i = 0; i < 32; i++) acc[i] = 0.f;

    const float* sb = s1 + (size_t)b * C1 * H1 * W1;

    for (int ic = 0; ic < 16; ic++) {
        const float* sc = sb + (size_t)ic * (H1 * W1);
#pragma unroll
        for (int ky = 0; ky < 3; ky++) {
            int iy = oy * 2 - 1 + ky;
            if ((unsigned)iy >= (unsigned)H1) continue;
            const float* sr = sc + iy * W1;
#pragma unroll
            for (int kx = 0; kx < 3; kx++) {
                int ix = ox * 2 - 1 + kx;
                if ((unsigned)ix >= (unsigned)W1) continue;
                float v = __ldg(sr + ix);
                const float4* wk = (const float4*)(ws + (ic * 9 + ky * 3 + kx) * 32);
#pragma unroll
                for (int j = 0; j < 8; j++) {
                    float4 w = wk[j];
                    acc[4*j+0] = fmaf(v, w.x, acc[4*j+0]);
                    acc[4*j+1] = fmaf(v, w.y, acc[4*j+1]);
                    acc[4*j+2] = fmaf(v, w.z, acc[4*j+2]);
                    acc[4*j+3] = fmaf(v, w.w, acc[4*j+3]);
                }
            }
        }
    }

    size_t base = (size_t)b * C2 * H2 * W2 + (size_t)oy * W2 + ox;
#pragma unroll
    for (int oc = 0; oc < 32; oc++) {
        size_t o = base + (size_t)oc * (H2 * W2);
        float m = m2[o] * 0.5f + acc[oc];
        bool sp = (m >= 1.0f);
        m2[o] = sp ? 0.f : m;
    }
}

// ---------------------------------------------------------------------------
// Kernel C: decoder conv (32->64, 3x3, s1, p1) + bias + relu
// grid.y = 2 halves of 32 output channels each.
// ---------------------------------------------------------------------------
__global__ void k_convd(const float* __restrict__ m2,
                        const float* __restrict__ wd,
                        const float* __restrict__ bd,
                        float* __restrict__ h1)
{
    __shared__ __align__(16) float ws[288 * 32];   // [(ic*9+kk)][ocl]
    int half = blockIdx.y;
    for (int i = threadIdx.x; i < 9216; i += blockDim.x) {
        int ol = i & 31, r = i >> 5;
        ws[i] = wd[(size_t)(half * 32 + ol) * 288 + r];
    }
    __syncthreads();

    int idx = blockIdx.x * blockDim.x + threadIdx.x;
    if (idx >= BATCH * H2 * W2) return;
    int ox = idx % W2;
    int tmp = idx / W2;
    int oy = tmp % H2;
    int b  = tmp / H2;

    float acc[32];
#pragma unroll
    for (int i = 0; i < 32; i++) acc[i] = 0.f;

    const float* xb = m2 + (size_t)b * C2 * H2 * W2;

    for (int ic = 0; ic < 32; ic++) {
        const float* xc = xb + (size_t)ic * (H2 * W2);
#pragma unroll
        for (int ky = 0; ky < 3; ky++) {
            int iy = oy - 1 + ky;
            if ((unsigned)iy >= (unsigned)H2) continue;
            const float* xr = xc + iy * W2;
#pragma unroll
            for (int kx = 0; kx < 3; kx++) {
                int ix = ox - 1 + kx;
                if ((unsigned)ix >= (unsigned)W2) continue;
                float v = __ldg(xr + ix);
                const float4* wk = (const float4*)(ws + (ic * 9 + ky * 3 + kx) * 32);
#pragma unroll
                for (int j = 0; j < 8; j++) {
                    float4 w = wk[j];
                    acc[4*j+0] = fmaf(v, w.x, acc[4*j+0]);
                    acc[4*j+1] = fmaf(v, w.y, acc[4*j+1]);
                    acc[4*j+2] = fmaf(v, w.z, acc[4*j+2]);
                    acc[4*j+3] = fmaf(v, w.w, acc[4*j+3]);
                }
            }
        }
    }

    size_t pix = (size_t)oy * W2 + ox;
#pragma unroll
    for (int ol = 0; ol < 32; ol++) {
        int oc = half * 32 + ol;
        float v = acc[ol] + __ldg(bd + oc);
        h1[((size_t)b * CD + oc) * (H2 * W2) + pix] = fmaxf(v, 0.f);
    }
}

// ---------------------------------------------------------------------------
// Kernel D: convT1 (64->32, 4x4, s2, p1) + bias + relu  (gather form)
// grid.y = 4 groups of 8 output channels.
// y[oc,oy,ox] = sum_{ic,ky,kx valid} x[ic,iy,ix] * w[ic,oc,ky,kx]
//   with iy = (oy+1-ky)/2 requiring parity match.
// ---------------------------------------------------------------------------
__global__ void k_convT1(const float* __restrict__ h1,
                         const float* __restrict__ wt1,
                         const float* __restrict__ bt1,
                         float* __restrict__ h2)
{
    __shared__ __align__(16) float ws[16 * 64 * 8];   // [kk][ic][ol8] = 32KB
    int g = blockIdx.y;
    for (int i = threadIdx.x; i < 8192; i += blockDim.x) {
        int ol = i & 7, ic = (i >> 3) & 63, kk = i >> 9;
        ws[i] = wt1[(size_t)ic * 512 + (size_t)(g * 8 + ol) * 16 + kk];
    }
    __syncthreads();

    int idx = blockIdx.x * blockDim.x + threadIdx.x;
    if (idx >= BATCH * H3 * W3) return;
    int ox = idx % W3;
    int tmp = idx / W3;
    int oy = tmp % H3;
    int b  = tmp / H3;

    float acc[8];
#pragma unroll
    for (int i = 0; i < 8; i++) acc[i] = 0.f;

    int ky0 = (oy & 1) ? 0 : 1;
    int kx0 = (ox & 1) ? 0 : 1;
    const float* hb = h1 + (size_t)b * CD * (H2 * W2);

#pragma unroll
    for (int dy = 0; dy < 2; dy++) {
        int ky = ky0 + 2 * dy;
        int iy = (oy + 1 - ky) >> 1;
        if ((unsigned)iy >= (unsigned)H2) continue;
#pragma unroll
        for (int dx = 0; dx < 2; dx++) {
            int kx = kx0 + 2 * dx;
            int ix = (ox + 1 - kx) >> 1;
            if ((unsigned)ix >= (unsigned)W2) continue;
            const float4* wk = (const float4*)(ws + (ky * 4 + kx) * 512);
            const float* hp = hb + (size_t)iy * W2 + ix;
            for (int ic = 0; ic < 64; ic++) {
                float v = __ldg(hp + (size_t)ic * (H2 * W2));
                float4 wA = wk[ic * 2];
                float4 wB = wk[ic * 2 + 1];
                acc[0] = fmaf(v, wA.x, acc[0]);
                acc[1] = fmaf(v, wA.y, acc[1]);
                acc[2] = fmaf(v, wA.z, acc[2]);
                acc[3] = fmaf(v, wA.w, acc[3]);
                acc[4] = fmaf(v, wB.x, acc[4]);
                acc[5] = fmaf(v, wB.y, acc[5]);
                acc[6] = fmaf(v, wB.z, acc[6]);
                acc[7] = fmaf(v, wB.w, acc[7]);
            }
        }
    }

    size_t pix = (size_t)oy * W3 + ox;
#pragma unroll
    for (int ol = 0; ol < 8; ol++) {
        int oc = g * 8 + ol;
        float v = acc[ol] + __ldg(bt1 + oc);
        h2[((size_t)b * C2 + oc) * (H3 * W3) + pix] = fmaxf(v, 0.f);
    }
}

// ---------------------------------------------------------------------------
// Kernel E: convT2 (32->2, 4x4, s2, p1) + bias + softplus, writes output
// out layout: [ch0 (B,100,368)] then [ch1 (B,100,368)]
// ---------------------------------------------------------------------------
__global__ void k_convT2(const float* __restrict__ h2,
                         const float* __restrict__ wt2,
                         const float* __restrict__ bt2,
                         float* __restrict__ out)
{
    __shared__ float ws[16 * 32 * 2];   // [kk][ic][oc]
    for (int i = threadIdx.x; i < 1024; i += blockDim.x) {
        int oc = i & 1, ic = (i >> 1) & 31, kk = i >> 6;
        ws[i] = wt2[(size_t)ic * 32 + oc * 16 + kk];
    }
    __syncthreads();

    int idx = blockIdx.x * blockDim.x + threadIdx.x;
    if (idx >= BATCH * H4 * W4) return;
    int ox = idx % W4;
    int tmp = idx / W4;
    int oy = tmp % H4;
    int b  = tmp / H4;

    float a0 = __ldg(bt2 + 0);
    float a1 = __ldg(bt2 + 1);

    int ky0 = (oy & 1) ? 0 : 1;
    int kx0 = (ox & 1) ? 0 : 1;
    const float* hb = h2 + (size_t)b * C2 * (H3 * W3);

#pragma unroll
    for (int dy = 0; dy < 2; dy++) {
        int ky = ky0 + 2 * dy;
        int iy = (oy + 1 - ky) >> 1;
        if ((unsigned)iy >= (unsigned)H3) continue;
#pragma unroll
        for (int dx = 0; dx < 2; dx++) {
            int kx = kx0 + 2 * dx;
            int ix = (ox + 1 - kx) >> 1;
            if ((unsigned)ix >= (unsigned)W3) continue;
            const float* wk = ws + (ky * 4 + kx) * 64;
            const float* hp = hb + (size_t)iy * W3 + ix;
#pragma unroll
            for (int ic = 0; ic < 32; ic++) {
                float v = __ldg(hp + (size_t)ic * (H3 * W3));
                a0 = fmaf(v, wk[ic * 2],     a0);
                a1 = fmaf(v, wk[ic * 2 + 1], a1);
            }
        }
    }

    // stable softplus: max(x,0) + log1p(exp(-|x|))
    float o0 = fmaxf(a0, 0.f) + log1pf(expf(-fabsf(a0)));
    float o1 = fmaxf(a1, 0.f) + log1pf(expf(-fabsf(a1)));

    size_t pix = (size_t)b * (H4 * W4) + (size_t)oy * W4 + ox;
    out[pix] = o0;
    out[(size_t)BATCH * H4 * W4 + pix] = o1;
}

// ---------------------------------------------------------------------------
// Launch
// ---------------------------------------------------------------------------
extern "C" void kernel_launch(void* const* d_in, const int* in_sizes, int n_in,
                              void* d_out, int out_size)
{
    (void)in_sizes; (void)n_in; (void)out_size;
    const float* x   = (const float*)d_in[0];
    const float* w1  = (const float*)d_in[1];
    const float* w2  = (const float*)d_in[2];
    const float* wd  = (const float*)d_in[3];
    const float* bd  = (const float*)d_in[4];
    const float* wt1 = (const float*)d_in[5];
    const float* bt1 = (const float*)d_in[6];
    const float* wt2 = (const float*)d_in[7];
    const float* bt2 = (const float*)d_in[8];
    float* out = (float*)d_out;

    float *pm1, *ps1, *pm2, *ph1, *ph2;
    cudaGetSymbolAddress((void**)&pm1, g_m1);
    cudaGetSymbolAddress((void**)&ps1, g_s1);
    cudaGetSymbolAddress((void**)&pm2, g_m2);
    cudaGetSymbolAddress((void**)&ph1, g_h1);
    cudaGetSymbolAddress((void**)&ph2, g_h2);

    cudaMemsetAsync(pm1, 0, (size_t)M1_N * sizeof(float), 0);
    cudaMemsetAsync(pm2, 0, (size_t)M2_N * sizeof(float), 0);

    const int pixA = BATCH * H1 * W1;   // 294,400
    const int pixB = BATCH * H2 * W2;   // 73,600
    const int pixE = BATCH * H4 * W4;   // 1,177,600

    for (int t = 0; t < T_STEPS; t++) {
        k_conv1_lif<<<(pixA + 255) / 256, 256>>>(x, w1, pm1, ps1, t);
        k_conv2_lif<<<(pixB + 127) / 128, 128>>>(ps1, w2, pm2);
    }

    k_convd <<<dim3((pixB + 127) / 128, 2), 128>>>(pm2, wd, bd, ph1);
    k_convT1<<<dim3((pixA + 255) / 256, 4), 256>>>(ph1, wt1, bt1, ph2);
    k_convT2<<<(pixE + 255) / 256, 256>>>(ph2, wt2, bt2, out);
}

// round 3
// speedup vs baseline: 1.0870x; 1.0870x over previous
#include <cuda_runtime.h>
#include <cuda_bf16.h>
#include <math.h>

// ---------------------------------------------------------------------------
// SNN_CNN_Hybrid — fp32 exact, packed f32x2 FMA (Blackwell), pixel-paired.
// ---------------------------------------------------------------------------

#define T_STEPS 16
#define BATCH   32
#define H0 100
#define W0 368
#define C1 16
#define H1 50
#define W1 184
#define C2 32
#define H2 25
#define W2 92
#define CD 64
#define H3 50
#define W3 184
#define H4 100
#define W4 368

#define M1_N (BATCH*C1*H1*W1)
#define M2_N (BATCH*C2*H2*W2)
#define H1_N (BATCH*CD*H2*W2)
#define H2_N (BATCH*C2*H3*W3)

__device__ float g_m1[M1_N];
__device__ float g_s1[M1_N];
__device__ float g_m2[M2_N];
__device__ float g_h1[H1_N];
__device__ float g_h2[H2_N];

typedef unsigned long long u64;

__device__ __forceinline__ u64 pack2(float a, float b) {
    u64 r;
    asm("mov.b64 %0, {%1, %2};" : "=l"(r) : "f"(a), "f"(b));
    return r;
}
__device__ __forceinline__ u64 bcast2(float a) { return pack2(a, a); }
__device__ __forceinline__ void unpack2(u64 v, float& a, float& b) {
    asm("mov.b64 {%0, %1}, %2;" : "=f"(a), "=f"(b) : "l"(v));
}
__device__ __forceinline__ u64 ffma2(u64 a, u64 b, u64 c) {
    u64 d;
    asm("fma.rn.f32x2 %0, %1, %2, %3;" : "=l"(d) : "l"(a), "l"(b), "l"(c));
    return d;
}

// ---------------------------------------------------------------------------
// Kernel A: conv1 (1->16, 5x5, s2, p2) + LIF. Thread = (b, oy, 2 adjacent ox).
// ---------------------------------------------------------------------------
__global__ void k_conv1_lif(const float* __restrict__ x,
                            const float* __restrict__ w1,
                            float* __restrict__ m1,
                            float* __restrict__ s1,
                            int t)
{
    __shared__ __align__(16) float ws[25 * 16];   // [tap][oc]
    for (int i = threadIdx.x; i < 400; i += blockDim.x) {
        int oc = i & 15, tap = i >> 4;
        ws[i] = w1[oc * 25 + tap];
    }
    __syncthreads();

    int idx = blockIdx.x * blockDim.x + threadIdx.x;
    if (idx >= BATCH * H1 * (W1 / 2)) return;
    int xp  = idx % (W1 / 2);
    int tmp = idx / (W1 / 2);
    int oy  = tmp % H1;
    int b   = tmp / H1;
    int ox0 = 2 * xp;

    u64 acc[2][8];
#pragma unroll
    for (int p = 0; p < 2; p++)
#pragma unroll
        for (int i = 0; i < 8; i++) acc[p][i] = 0ull;

    const float* xb = x + ((size_t)t * BATCH + b) * (H0 * W0);

#pragma unroll
    for (int ky = 0; ky < 5; ky++) {
        int iy = oy * 2 - 2 + ky;
        if ((unsigned)iy >= (unsigned)H0) continue;
        const float* xr = xb + iy * W0;
        float v[7];
#pragma unroll
        for (int j = 0; j < 7; j++) {
            int ix = 4 * xp - 2 + j;
            v[j] = ((unsigned)ix < (unsigned)W0) ? __ldg(xr + ix) : 0.f;
        }
#pragma unroll
        for (int kx = 0; kx < 5; kx++) {
            u64 vv0 = bcast2(v[kx]);
            u64 vv1 = bcast2(v[kx + 2]);
            const ulonglong2* wp = (const ulonglong2*)(ws + (ky * 5 + kx) * 16);
#pragma unroll
            for (int j = 0; j < 4; j++) {
                ulonglong2 w = wp[j];
                acc[0][2*j]   = ffma2(vv0, w.x, acc[0][2*j]);
                acc[0][2*j+1] = ffma2(vv0, w.y, acc[0][2*j+1]);
                acc[1][2*j]   = ffma2(vv1, w.x, acc[1][2*j]);
                acc[1][2*j+1] = ffma2(vv1, w.y, acc[1][2*j+1]);
            }
        }
    }

    size_t base = (size_t)b * C1 * H1 * W1 + (size_t)oy * W1 + ox0;
#pragma unroll
    for (int j = 0; j < 8; j++) {
        float a0, a1, b0, b1;
        unpack2(acc[0][j], a0, a1);   // pixel0, oc 2j / 2j+1
        unpack2(acc[1][j], b0, b1);   // pixel1
        {
            size_t o = base + (size_t)(2*j) * (H1 * W1);
            float m = m1[o] * 0.5f + a0;
            bool sp = (m >= 1.0f);
            m1[o] = sp ? 0.f : m;  s1[o] = sp ? 1.f : 0.f;
            m = m1[o+1] * 0.5f + b0;
            sp = (m >= 1.0f);
            m1[o+1] = sp ? 0.f : m;  s1[o+1] = sp ? 1.f : 0.f;
        }
        {
            size_t o = base + (size_t)(2*j+1) * (H1 * W1);
            float m = m1[o] * 0.5f + a1;
            bool sp = (m >= 1.0f);
            m1[o] = sp ? 0.f : m;  s1[o] = sp ? 1.f : 0.f;
            m = m1[o+1] * 0.5f + b1;
            sp = (m >= 1.0f);
            m1[o+1] = sp ? 0.f : m;  s1[o+1] = sp ? 1.f : 0.f;
        }
    }
}

// ---------------------------------------------------------------------------
// Kernel B: conv2 (16->32, 3x3, s2, p1) + LIF. Thread = (b, oy, 2 adjacent ox),
// all 32 channels as 16 packed f32x2 accumulators per pixel.
// ---------------------------------------------------------------------------
__global__ void __launch_bounds__(128)
k_conv2_lif(const float* __restrict__ s1,
            const float* __restrict__ w2,
            float* __restrict__ m2)
{
    __shared__ __align__(16) float ws[144 * 32];   // [(ic*9+kk)][oc]
    for (int i = threadIdx.x; i < 4608; i += blockDim.x) {
        int oc = i & 31, r = i >> 5;
        ws[i] = w2[oc * 144 + r];
    }
    __syncthreads();

    int idx = blockIdx.x * blockDim.x + threadIdx.x;
    if (idx >= BATCH * H2 * (W2 / 2)) return;
    int xp  = idx % (W2 / 2);
    int tmp = idx / (W2 / 2);
    int oy  = tmp % H2;
    int b   = tmp / H2;

    u64 acc[2][16];
#pragma unroll
    for (int p = 0; p < 2; p++)
#pragma unroll
        for (int i = 0; i < 16; i++) acc[p][i] = 0ull;

    const float* sb = s1 + (size_t)b * C1 * H1 * W1;

    for (int ic = 0; ic < 16; ic++) {
        const float* sc = sb + (size_t)ic * (H1 * W1);
#pragma unroll
        for (int ky = 0; ky < 3; ky++) {
            int iy = oy * 2 - 1 + ky;
            if ((unsigned)iy >= (unsigned)H1) continue;
            const float* sr = sc + iy * W1;
            float v[5];
#pragma unroll
            for (int j = 0; j < 5; j++) {
                int ix = 4 * xp - 1 + j;
                v[j] = ((unsigned)ix < (unsigned)W1) ? __ldg(sr + ix) : 0.f;
            }
#pragma unroll
            for (int kx = 0; kx < 3; kx++) {
                u64 vv0 = bcast2(v[kx]);
                u64 vv1 = bcast2(v[kx + 2]);
                const ulonglong2* wp = (const ulonglong2*)(ws + (ic * 9 + ky * 3 + kx) * 32);
#pragma unroll
                for (int j = 0; j < 8; j++) {
                    ulonglong2 w = wp[j];
                    acc[0][2*j]   = ffma2(vv0, w.x, acc[0][2*j]);
                    acc[0][2*j+1] = ffma2(vv0, w.y, acc[0][2*j+1]);
                    acc[1][2*j]   = ffma2(vv1, w.x, acc[1][2*j]);
                    acc[1][2*j+1] = ffma2(vv1, w.y, acc[1][2*j+1]);
                }
            }
        }
    }

    size_t base = (size_t)b * C2 * H2 * W2 + (size_t)oy * W2 + 2 * xp;
#pragma unroll
    for (int j = 0; j < 16; j++) {
        float a0, a1, b0, b1;
        unpack2(acc[0][j], a0, a1);
        unpack2(acc[1][j], b0, b1);
        {
            size_t o = base + (size_t)(2*j) * (H2 * W2);
            float m = m2[o] * 0.5f + a0;
            m2[o] = (m >= 1.0f) ? 0.f : m;
            m = m2[o+1] * 0.5f + b0;
            m2[o+1] = (m >= 1.0f) ? 0.f : m;
        }
        {
            size_t o = base + (size_t)(2*j+1) * (H2 * W2);
            float m = m2[o] * 0.5f + a1;
            m2[o] = (m >= 1.0f) ? 0.f : m;
            m = m2[o+1] * 0.5f + b1;
            m2[o+1] = (m >= 1.0f) ? 0.f : m;
        }
    }
}

// ---------------------------------------------------------------------------
// Kernel C: decoder conv (32->64, 3x3, s1, p1) + bias + relu. grid.y = 2 halves.
// ---------------------------------------------------------------------------
__global__ void k_convd(const float* __restrict__ m2,
                        const float* __restrict__ wd,
                        const float* __restrict__ bd,
                        float* __restrict__ h1)
{
    __shared__ __align__(16) float ws[288 * 32];   // [(ic*9+kk)][ocl]
    int half = blockIdx.y;
    for (int i = threadIdx.x; i < 9216; i += blockDim.x) {
        int ol = i & 31, r = i >> 5;
        ws[i] = wd[(size_t)(half * 32 + ol) * 288 + r];
    }
    __syncthreads();

    int idx = blockIdx.x * blockDim.x + threadIdx.x;
    if (idx >= BATCH * H2 * W2) return;
    int ox = idx % W2;
    int tmp = idx / W2;
    int oy = tmp % H2;
    int b  = tmp / H2;

    u64 acc[16];
#pragma unroll
    for (int i = 0; i < 16; i++) acc[i] = 0ull;

    const float* xb = m2 + (size_t)b * C2 * H2 * W2;

    for (int ic = 0; ic < 32; ic++) {
        const float* xc = xb + (size_t)ic * (H2 * W2);
#pragma unroll
        for (int ky = 0; ky < 3; ky++) {
            int iy = oy - 1 + ky;
            if ((unsigned)iy >= (unsigned)H2) continue;
            const float* xr = xc + iy * W2;
#pragma unroll
            for (int kx = 0; kx < 3; kx++) {
                int ix = ox - 1 + kx;
                if ((unsigned)ix >= (unsigned)W2) continue;
                u64 vv = bcast2(__ldg(xr + ix));
                const ulonglong2* wp = (const ulonglong2*)(ws + (ic * 9 + ky * 3 + kx) * 32);
#pragma unroll
                for (int j = 0; j < 8; j++) {
                    ulonglong2 w = wp[j];
                    acc[2*j]   = ffma2(vv, w.x, acc[2*j]);
                    acc[2*j+1] = ffma2(vv, w.y, acc[2*j+1]);
                }
            }
        }
    }

    size_t pix = (size_t)oy * W2 + ox;
#pragma unroll
    for (int j = 0; j < 16; j++) {
        float a0, a1;
        unpack2(acc[j], a0, a1);
        int oc = half * 32 + 2 * j;
        h1[((size_t)b * CD + oc)     * (H2 * W2) + pix] = fmaxf(a0 + __ldg(bd + oc),     0.f);
        h1[((size_t)b * CD + oc + 1) * (H2 * W2) + pix] = fmaxf(a1 + __ldg(bd + oc + 1), 0.f);
    }
}

// ---------------------------------------------------------------------------
// Kernel D: convT1 (64->32, 4x4, s2, p1) + bias + relu. Gather form.
// blockIdx.y = parity combo (oy parity, ox parity). Thread = (b, oy, x-pair of
// same parity: ox_a, ox_a+2), all 32 oc packed.
// ---------------------------------------------------------------------------
__global__ void __launch_bounds__(128)
k_convT1(const float* __restrict__ h1,
         const float* __restrict__ wt1,
         const float* __restrict__ bt1,
         float* __restrict__ h2)
{
    // 4 taps used by this parity combo: ws[(dy*2+dx)][ic][oc]
    __shared__ __align__(16) float ws[4 * 64 * 32];   // 32 KB
    int q  = blockIdx.y;
    int py = q >> 1, px = q & 1;
    int ky0 = py ? 0 : 1;
    int kx0 = px ? 0 : 1;
    for (int i = threadIdx.x; i < 8192; i += blockDim.x) {
        int oc = i & 31, ic = (i >> 5) & 63, comb = i >> 11;
        int dy = comb >> 1, dx = comb & 1;
        int ky = ky0 + 2 * dy, kx = kx0 + 2 * dx;
        ws[i] = wt1[(size_t)ic * 512 + (size_t)oc * 16 + ky * 4 + kx];
    }
    __syncthreads();

    int idx = blockIdx.x * blockDim.x + threadIdx.x;
    if (idx >= BATCH * (H3 / 2) * (W3 / 4)) return;
    int k   = idx % (W3 / 4);           // 46 x-pairs per parity
    int tmp = idx / (W3 / 4);
    int oy2 = tmp % (H3 / 2);           // 25 rows per parity
    int b   = tmp / (H3 / 2);
    int oy   = 2 * oy2 + py;
    int ox_a = px + 4 * k;              // ox_b = ox_a + 2

    int Y = (oy + 1 - ky0) >> 1;
    int X = (ox_a + 1 - kx0) >> 1;

    u64 acc[2][16];
#pragma unroll
    for (int p = 0; p < 2; p++)
#pragma unroll
        for (int i = 0; i < 16; i++) acc[p][i] = 0ull;

    const float* hb = h1 + (size_t)b * CD * (H2 * W2);

#pragma unroll
    for (int dy = 0; dy < 2; dy++) {
        int iy = Y - dy;
        if ((unsigned)iy >= (unsigned)H2) continue;
        const float* hr = hb + (size_t)iy * W2;
        for (int ic = 0; ic < 64; ic++) {
            const float* hp = hr + (size_t)ic * (H2 * W2);
            float v[3];
#pragma unroll
            for (int j = 0; j < 3; j++) {
                int ix = X - 1 + j;
                v[j] = ((unsigned)ix < (unsigned)W2) ? __ldg(hp + ix) : 0.f;
            }
#pragma unroll
            for (int dx = 0; dx < 2; dx++) {
                // pixel a uses col (X - dx) = v[1-dx]; pixel b uses v[2-dx]
                u64 va = bcast2(v[1 - dx]);
                u64 vb = bcast2(v[2 - dx]);
                const ulonglong2* wp = (const ulonglong2*)(ws + ((dy * 2 + dx) * 64 + ic) * 32);
#pragma unroll
                for (int j = 0; j < 8; j++) {
                    ulonglong2 w = wp[j];
                    acc[0][2*j]   = ffma2(va, w.x, acc[0][2*j]);
                    acc[0][2*j+1] = ffma2(va, w.y, acc[0][2*j+1]);
                    acc[1][2*j]   = ffma2(vb, w.x, acc[1][2*j]);
                    acc[1][2*j+1] = ffma2(vb, w.y, acc[1][2*j+1]);
                }
            }
        }
    }

    size_t pixa = (size_t)oy * W3 + ox_a;
#pragma unroll
    for (int j = 0; j < 16; j++) {
        float a0, a1, b0, b1;
        unpack2(acc[0][j], a0, a1);
        unpack2(acc[1][j], b0, b1);
        int oc = 2 * j;
        float bias0 = __ldg(bt1 + oc), bias1 = __ldg(bt1 + oc + 1);
        size_t o0 = ((size_t)b * C2 + oc)     * (H3 * W3) + pixa;
        size_t o1 = ((size_t)b * C2 + oc + 1) * (H3 * W3) + pixa;
        h2[o0]     = fmaxf(a0 + bias0, 0.f);
        h2[o0 + 2] = fmaxf(b0 + bias0, 0.f);
        h2[o1]     = fmaxf(a1 + bias1, 0.f);
        h2[o1 + 2] = fmaxf(b1 + bias1, 0.f);
    }
}

// ---------------------------------------------------------------------------
// Kernel E: convT2 (32->2, 4x4, s2, p1) + bias + softplus.
// blockIdx.y = parity combo. Thread = 2x2 same-parity output tile; the 2
// output channels live in one f32x2 accumulator per pixel.
// ---------------------------------------------------------------------------
__global__ void k_convT2(const float* __restrict__ h2,
                         const float* __restrict__ wt2,
                         const float* __restrict__ bt2,
                         float* __restrict__ out)
{
    __shared__ __align__(16) float ws[4 * 32 * 2];   // [(dy*2+dx)][ic][oc]
    int q  = blockIdx.y;
    int py = q >> 1, px = q & 1;
    int ky0 = py ? 0 : 1;
    int kx0 = px ? 0 : 1;
    for (int i = threadIdx.x; i < 256; i += blockDim.x) {
        int oc = i & 1, ic = (i >> 1) & 31, comb = i >> 6;
        int dy = comb >> 1, dx = comb & 1;
        int ky = ky0 + 2 * dy, kx = kx0 + 2 * dx;
        ws[i] = wt2[(size_t)ic * 32 + oc * 16 + ky * 4 + kx];
    }
    __syncthreads();

    int idx = blockIdx.x * blockDim.x + threadIdx.x;
    if (idx >= BATCH * (H4 / 4) * (W4 / 4)) return;
    int k   = idx % (W4 / 4);           // 92 x-pairs per parity
    int tmp = idx / (W4 / 4);
    int j2  = tmp % (H4 / 4);           // 25 y-pairs per parity
    int b   = tmp / (H4 / 4);
    int oy_a = py + 4 * j2;             // oy_b = oy_a + 2
    int ox_a = px + 4 * k;              // ox_b = ox_a + 2

    int Y = (oy_a + 1 - ky0) >> 1;
    int X = (ox_a + 1 - kx0) >> 1;

    u64 acc[4];  // [yi*2+xj], each = (ch0, ch1)
    u64 binit = pack2(__ldg(bt2 + 0), __ldg(bt2 + 1));
#pragma unroll
    for (int i = 0; i < 4; i++) acc[i] = binit;

    const u64* wsp = (const u64*)ws;    // [(dy*2+dx)*32 + ic]
    const float* hb = h2 + (size_t)b * C2 * (H3 * W3);

    for (int ic = 0; ic < 32; ic++) {
        const float* hc = hb + (size_t)ic * (H3 * W3);
        float v[3][3];
#pragma unroll
        for (int r = 0; r < 3; r++) {
            int iy = Y - 1 + r;
            bool rok = ((unsigned)iy < (unsigned)H3);
            const float* hr = hc + (size_t)iy * W3;
#pragma unroll
            for (int c = 0; c < 3; c++) {
                int ix = X - 1 + c;
                v[r][c] = (rok && (unsigned)ix < (unsigned)W3) ? __ldg(hr + ix) : 0.f;
            }
        }
#pragma unroll
        for (int dy = 0; dy < 2; dy++) {
#pragma unroll
            for (int dx = 0; dx < 2; dx++) {
                u64 w = wsp[(dy * 2 + dx) * 32 + ic];
                // pixel (yi, xj) uses v[1 + yi - dy][1 + xj - dx]
#pragma unroll
                for (int yi = 0; yi < 2; yi++)
#pragma unroll
                    for (int xj = 0; xj < 2; xj++)
                        acc[yi * 2 + xj] = ffma2(bcast2(v[1 + yi - dy][1 + xj - dx]), w,
                                                 acc[yi * 2 + xj]);
            }
        }
    }

#pragma unroll
    for (int yi = 0; yi < 2; yi++) {
#pragma unroll
        for (int xj = 0; xj < 2; xj++) {
            float a0, a1;
            unpack2(acc[yi * 2 + xj], a0, a1);
            float o0 = fmaxf(a0, 0.f) + log1pf(expf(-fabsf(a0)));
            float o1 = fmaxf(a1, 0.f) + log1pf(expf(-fabsf(a1)));
            int oy = oy_a + 2 * yi, ox = ox_a + 2 * xj;
            size_t pix = (size_t)b * (H4 * W4) + (size_t)oy * W4 + ox;
            out[pix] = o0;
            out[(size_t)BATCH * H4 * W4 + pix] = o1;
        }
    }
}

// ---------------------------------------------------------------------------
// Launch
// ---------------------------------------------------------------------------
extern "C" void kernel_launch(void* const* d_in, const int* in_sizes, int n_in,
                              void* d_out, int out_size)
{
    (void)in_sizes; (void)n_in; (void)out_size;
    const float* x   = (const float*)d_in[0];
    const float* w1  = (const float*)d_in[1];
    const float* w2  = (const float*)d_in[2];
    const float* wd  = (const float*)d_in[3];
    const float* bd  = (const float*)d_in[4];
    const float* wt1 = (const float*)d_in[5];
    const float* bt1 = (const float*)d_in[6];
    const float* wt2 = (const float*)d_in[7];
    const float* bt2 = (const float*)d_in[8];
    float* out = (float*)d_out;

    float *pm1, *ps1, *pm2, *ph1, *ph2;
    cudaGetSymbolAddress((void**)&pm1, g_m1);
    cudaGetSymbolAddress((void**)&ps1, g_s1);
    cudaGetSymbolAddress((void**)&pm2, g_m2);
    cudaGetSymbolAddress((void**)&ph1, g_h1);
    cudaGetSymbolAddress((void**)&ph2, g_h2);

    cudaMemsetAsync(pm1, 0, (size_t)M1_N * sizeof(float), 0);
    cudaMemsetAsync(pm2, 0, (size_t)M2_N * sizeof(float), 0);

    const int nA = BATCH * H1 * (W1 / 2);          // 147200
    const int nB = BATCH * H2 * (W2 / 2);          // 36800
    const int nC = BATCH * H2 * W2;                // 73600
    const int nD = BATCH * (H3 / 2) * (W3 / 4);    // 36800 per parity combo
    const int nE = BATCH * (H4 / 4) * (W4 / 4);    // 73600 per parity combo

    for (int t = 0; t < T_STEPS; t++) {
        k_conv1_lif<<<(nA + 255) / 256, 256>>>(x, w1, pm1, ps1, t);
        k_conv2_lif<<<(nB + 127) / 128, 128>>>(ps1, w2, pm2);
    }

    k_convd <<<dim3((nC + 127) / 128, 2), 128>>>(pm2, wd, bd, ph1);
    k_convT1<<<dim3((nD + 127) / 128, 4), 128>>>(ph1, wt1, bt1, ph2);
    k_convT2<<<dim3((nE + 127) / 128, 4), 128>>>(ph2, wt2, bt2, out);
}

// round 4
// speedup vs baseline: 1.1577x; 1.0651x over previous
#include <cuda_runtime.h>
#include <cuda_bf16.h>
#include <math.h>

// ---------------------------------------------------------------------------
// SNN_CNN_Hybrid — batch-on-lanes recurrent loop (coalesced, high occupancy),
// binary activations as uint8, packed f32x2 FMA. Decoder unchanged.
// ---------------------------------------------------------------------------

#define T_STEPS 16
#define BATCH   32
#define H0 100
#define W0 368
#define P0 (H0*W0)            // 36800
#define C1 16
#define H1 50
#define W1 184
#define P1 (H1*W1)            // 9200
#define C2 32
#define H2 25
#define W2 92
#define P2 (H2*W2)            // 2300
#define CD 64
#define H3 50
#define W3 184
#define H4 100
#define W4 368

#define M1_N (C1*P1*BATCH)            // 4,710,400 floats
#define M2_N (C2*P2*BATCH)            // 2,355,200 floats
#define H1_N (BATCH*CD*P2)
#define H2_N (BATCH*C2*H3*W3)

// Persistent scratch (static device globals; no runtime allocation)
__device__ unsigned char g_x8[T_STEPS*P0*BATCH];   // x transposed: [t][p0][b], binary
__device__ float         g_m1[M1_N];               // [oc][p1][b]
__device__ unsigned char g_s1[C1*P1*BATCH];        // [ic][p1][b], binary
__device__ float         g_m2[M2_N];               // [oc][p2][b]
__device__ float         g_m2T[M2_N];              // [b][oc][p2]  (old layout, for decoder)
__device__ float         g_h1[H1_N];
__device__ float         g_h2[H2_N];

typedef unsigned long long u64;

__device__ __forceinline__ u64 pack2(float a, float b) {
    u64 r;
    asm("mov.b64 %0, {%1, %2};" : "=l"(r) : "f"(a), "f"(b));
    return r;
}
__device__ __forceinline__ u64 bcast2(float a) { return pack2(a, a); }
__device__ __forceinline__ void unpack2(u64 v, float& a, float& b) {
    asm("mov.b64 {%0, %1}, %2;" : "=f"(a), "=f"(b) : "l"(v));
}
__device__ __forceinline__ u64 ffma2(u64 a, u64 b, u64 c) {
    u64 d;
    asm("fma.rn.f32x2 %0, %1, %2, %3;" : "=l"(d) : "l"(a), "l"(b), "l"(c));
    return d;
}

// ---------------------------------------------------------------------------
// Transpose x: [t][b][p0] float -> [t][p0][b] uint8 (values are exactly 0/1).
// Tiled 32x32 via smem. grid=(P0/32, T), block=(32,8).
// ---------------------------------------------------------------------------
__global__ void k_transpose_x(const float* __restrict__ x,
                              unsigned char* __restrict__ x8)
{
    __shared__ float tile[32][33];
    int t  = blockIdx.y;
    int p0 = blockIdx.x * 32;
    int tx = threadIdx.x;
#pragma unroll
    for (int yy = 0; yy < 4; yy++) {
        int b = threadIdx.y + yy * 8;
        tile[b][tx] = x[((size_t)(t * BATCH + b)) * P0 + p0 + tx];
    }
    __syncthreads();
#pragma unroll
    for (int yy = 0; yy < 4; yy++) {
        int b = threadIdx.y + yy * 8;
        // out[(t*P0 + p0 + tx)*32 + b] ; coalesced over tx within a b-row? No:
        // coalesce over lanes: lane=tx varies p -> stride 32 bytes. Use b on tx:
        x8[((size_t)t * P0 + p0 + b) * BATCH + tx] =
            (unsigned char)tile[b == b ? (threadIdx.y + yy * 8) : 0][0] * 0; // placeholder
    }
}

// NOTE: the kernel above is replaced by the correct version below; kept name.
__global__ void k_transpose_x2(const float* __restrict__ x,
                               unsigned char* __restrict__ x8)
{
    __shared__ float tile[32][33];   // [b][p_local]
    int t  = blockIdx.y;
    int p0 = blockIdx.x * 32;
    int tx = threadIdx.x;
#pragma unroll
    for (int yy = 0; yy < 4; yy++) {
        int b = threadIdx.y + yy * 8;
        tile[b][tx] = x[((size_t)(t * BATCH + b)) * P0 + p0 + tx];   // coalesced over p
    }
    __syncthreads();
#pragma unroll
    for (int yy = 0; yy < 4; yy++) {
        int pl = threadIdx.y + yy * 8;
        // write out[t][p0+pl][b=tx] : 32 consecutive bytes per warp-row
        x8[((size_t)t * P0 + p0 + pl) * BATCH + tx] = (unsigned char)tile[tx][pl];
    }
}

// ---------------------------------------------------------------------------
// Transpose m2: [oc][p2][b] -> [b][oc][p2]  (r = oc*P2+p2, R = 73600)
// ---------------------------------------------------------------------------
__global__ void k_transpose_m2(const float* __restrict__ m2,
                               float* __restrict__ m2T)
{
    __shared__ float tile[32][33];   // [r_local][b]
    const int R = C2 * P2;           // 73600
    int r0 = blockIdx.x * 32;
    int tx = threadIdx.x;
#pragma unroll
    for (int yy = 0; yy < 4; yy++) {
        int rl = threadIdx.y + yy * 8;
        tile[rl][tx] = m2[(size_t)(r0 + rl) * BATCH + tx];   // coalesced over b
    }
    __syncthreads();
#pragma unroll
    for (int yy = 0; yy < 4; yy++) {
        int b = threadIdx.y + yy * 8;
        m2T[(size_t)b * R + r0 + tx] = tile[tx][b];          // coalesced over r
    }
}

// ---------------------------------------------------------------------------
// Kernel A: conv1 (1->16, 5x5, s2, p2) + LIF.
// Warp = (oy, pair of adjacent ox); lane = b. All 16 oc packed (8 u64).
// grid = 575 blocks x 256 threads = 4600 warps (= 50 * 92 pairs).
// ---------------------------------------------------------------------------
__global__ void __launch_bounds__(256)
k_conv1_lif(const unsigned char* __restrict__ xT,
            const float* __restrict__ w1,
            float* __restrict__ m1,
            unsigned char* __restrict__ s1,
            int t)
{
    __shared__ __align__(16) float ws[25 * 16];   // [tap][oc]
    for (int i = threadIdx.x; i < 400; i += 256) {
        int oc = i & 15, tap = i >> 4;
        ws[i] = w1[oc * 25 + tap];
    }
    __syncthreads();

    int wg   = blockIdx.x * 8 + (threadIdx.x >> 5);   // 0..4599
    int lane = threadIdx.x & 31;
    int xp = wg % (W1 / 2);          // 0..91
    int oy = wg / (W1 / 2);          // 0..49

    u64 acc[2][8];
#pragma unroll
    for (int p = 0; p < 2; p++)
#pragma unroll
        for (int i = 0; i < 8; i++) acc[p][i] = 0ull;

    const unsigned char* xb = xT + (size_t)t * P0 * BATCH;

#pragma unroll
    for (int ky = 0; ky < 5; ky++) {
        int iy = oy * 2 - 2 + ky;
        if ((unsigned)iy >= (unsigned)H0) continue;
        const unsigned char* xr = xb + (size_t)iy * W0 * BATCH;
        float v[7];
#pragma unroll
        for (int j = 0; j < 7; j++) {
            int ix = 4 * xp - 2 + j;
            v[j] = ((unsigned)ix < (unsigned)W0)
                 ? (float)xr[(size_t)ix * BATCH + lane] : 0.f;
        }
#pragma unroll
        for (int kx = 0; kx < 5; kx++) {
            u64 vv0 = bcast2(v[kx]);
            u64 vv1 = bcast2(v[kx + 2]);
            const ulonglong2* wp = (const ulonglong2*)(ws + (ky * 5 + kx) * 16);
#pragma unroll
            for (int j = 0; j < 4; j++) {
                ulonglong2 w = wp[j];
                acc[0][2*j]   = ffma2(vv0, w.x, acc[0][2*j]);
                acc[0][2*j+1] = ffma2(vv0, w.y, acc[0][2*j+1]);
                acc[1][2*j]   = ffma2(vv1, w.x, acc[1][2*j]);
                acc[1][2*j+1] = ffma2(vv1, w.y, acc[1][2*j+1]);
            }
        }
    }

    int p1 = oy * W1 + 2 * xp;   // pixel A; pixel B = p1+1
#pragma unroll
    for (int j = 0; j < 8; j++) {
        float a0, a1, b0, b1;
        unpack2(acc[0][j], a0, a1);   // pixel A: oc 2j, 2j+1
        unpack2(acc[1][j], b0, b1);   // pixel B
        {
            size_t oA = ((size_t)(2*j) * P1 + p1) * BATCH + lane;
            float m = m1[oA] * 0.5f + a0;
            bool sp = (m >= 1.0f);
            m1[oA] = sp ? 0.f : m;  s1[oA] = sp ? 1 : 0;
            size_t oB = oA + BATCH;
            m = m1[oB] * 0.5f + b0;
            sp = (m >= 1.0f);
            m1[oB] = sp ? 0.f : m;  s1[oB] = sp ? 1 : 0;
        }
        {
            size_t oA = ((size_t)(2*j+1) * P1 + p1) * BATCH + lane;
            float m = m1[oA] * 0.5f + a1;
            bool sp = (m >= 1.0f);
            m1[oA] = sp ? 0.f : m;  s1[oA] = sp ? 1 : 0;
            size_t oB = oA + BATCH;
            m = m1[oB] * 0.5f + b1;
            sp = (m >= 1.0f);
            m1[oB] = sp ? 0.f : m;  s1[oB] = sp ? 1 : 0;
        }
    }
}

// ---------------------------------------------------------------------------
// Kernel B: conv2 (16->32, 3x3, s2, p1) + LIF.
// Warp = (oy, pair of adjacent ox, ocg of 8 oc); lane = b.
// Block = 8 warps = 2 pixel-pairs x 4 ocg. grid = 575 blocks = 4600 warps.
// ---------------------------------------------------------------------------
__global__ void __launch_bounds__(256)
k_conv2_lif(const unsigned char* __restrict__ s1,
            const float* __restrict__ w2,
            float* __restrict__ m2)
{
    __shared__ __align__(16) float ws[4 * 144 * 8];   // [ocg][(ic*9+kk)][ocl]
    for (int i = threadIdx.x; i < 4608; i += 256) {
        int ocl = i & 7;
        int r   = (i >> 3) % 144;
        int ocg = i / (144 * 8);
        ws[i] = w2[(size_t)(ocg * 8 + ocl) * 144 + r];
    }
    __syncthreads();

    int wib  = threadIdx.x >> 5;                 // 0..7
    int lane = threadIdx.x & 31;
    int ocg  = wib & 3;
    int pw   = blockIdx.x * 2 + (wib >> 2);      // pixel-pair index 0..1149
    int xp = pw % (W2 / 2);                      // 0..45
    int oy = pw / (W2 / 2);                      // 0..24

    u64 acc[2][4];
#pragma unroll
    for (int p = 0; p < 2; p++)
#pragma unroll
        for (int i = 0; i < 4; i++) acc[p][i] = 0ull;

    for (int ic = 0; ic < 16; ic++) {
        const unsigned char* sc = s1 + (size_t)ic * P1 * BATCH;
#pragma unroll
        for (int ky = 0; ky < 3; ky++) {
            int iy = oy * 2 - 1 + ky;
            if ((unsigned)iy >= (unsigned)H1) continue;
            const unsigned char* sr = sc + (size_t)iy * W1 * BATCH;
            float v[5];
#pragma unroll
            for (int j = 0; j < 5; j++) {
                int ix = 4 * xp - 1 + j;
                v[j] = ((unsigned)ix < (unsigned)W1)
                     ? (float)sr[(size_t)ix * BATCH + lane] : 0.f;
            }
#pragma unroll
            for (int kx = 0; kx < 3; kx++) {
                u64 vv0 = bcast2(v[kx]);
                u64 vv1 = bcast2(v[kx + 2]);
                const ulonglong2* wp =
                    (const ulonglong2*)(ws + ((ocg * 144) + ic * 9 + ky * 3 + kx) * 8);
                ulonglong2 wA = wp[0];
                ulonglong2 wB = wp[1];
                acc[0][0] = ffma2(vv0, wA.x, acc[0][0]);
                acc[0][1] = ffma2(vv0, wA.y, acc[0][1]);
                acc[0][2] = ffma2(vv0, wB.x, acc[0][2]);
                acc[0][3] = ffma2(vv0, wB.y, acc[0][3]);
                acc[1][0] = ffma2(vv1, wA.x, acc[1][0]);
                acc[1][1] = ffma2(vv1, wA.y, acc[1][1]);
                acc[1][2] = ffma2(vv1, wB.x, acc[1][2]);
                acc[1][3] = ffma2(vv1, wB.y, acc[1][3]);
            }
        }
    }

    int p2 = oy * W2 + 2 * xp;   // pixel A; B = p2+1
#pragma unroll
    for (int j = 0; j < 4; j++) {
        float a0, a1, b0, b1;
        unpack2(acc[0][j], a0, a1);
        unpack2(acc[1][j], b0, b1);
        int oc = ocg * 8 + 2 * j;
        {
            size_t oA = ((size_t)oc * P2 + p2) * BATCH + lane;
            float m = m2[oA] * 0.5f + a0;
            m2[oA] = (m >= 1.0f) ? 0.f : m;
            size_t oB = oA + BATCH;
            m = m2[oB] * 0.5f + b0;
            m2[oB] = (m >= 1.0f) ? 0.f : m;
        }
        {
            size_t oA = ((size_t)(oc + 1) * P2 + p2) * BATCH + lane;
            float m = m2[oA] * 0.5f + a1;
            m2[oA] = (m >= 1.0f) ? 0.f : m;
            size_t oB = oA + BATCH;
            m = m2[oB] * 0.5f + b1;
            m2[oB] = (m >= 1.0f) ? 0.f : m;
        }
    }
}

// ---------------------------------------------------------------------------
// Kernel C: decoder conv (32->64, 3x3, s1, p1) + bias + relu. (unchanged)
// Reads m2T in [b][ic][H2][W2] layout.
// ---------------------------------------------------------------------------
__global__ void k_convd(const float* __restrict__ m2,
                        const float* __restrict__ wd,
                        const float* __restrict__ bd,
                        float* __restrict__ h1)
{
    __shared__ __align__(16) float ws[288 * 32];
    int half = blockIdx.y;
    for (int i = threadIdx.x; i < 9216; i += blockDim.x) {
        int ol = i & 31, r = i >> 5;
        ws[i] = wd[(size_t)(half * 32 + ol) * 288 + r];
    }
    __syncthreads();

    int idx = blockIdx.x * blockDim.x + threadIdx.x;
    if (idx >= BATCH * P2) return;
    int ox = idx % W2;
    int tmp = idx / W2;
    int oy = tmp % H2;
    int b  = tmp / H2;

    u64 acc[16];
#pragma unroll
    for (int i = 0; i < 16; i++) acc[i] = 0ull;

    const float* xb = m2 + (size_t)b * C2 * P2;

    for (int ic = 0; ic < 32; ic++) {
        const float* xc = xb + (size_t)ic * P2;
#pragma unroll
        for (int ky = 0; ky < 3; ky++) {
            int iy = oy - 1 + ky;
            if ((unsigned)iy >= (unsigned)H2) continue;
            const float* xr = xc + iy * W2;
#pragma unroll
            for (int kx = 0; kx < 3; kx++) {
                int ix = ox - 1 + kx;
                if ((unsigned)ix >= (unsigned)W2) continue;
                u64 vv = bcast2(__ldg(xr + ix));
                const ulonglong2* wp = (const ulonglong2*)(ws + (ic * 9 + ky * 3 + kx) * 32);
#pragma unroll
                for (int j = 0; j < 8; j++) {
                    ulonglong2 w = wp[j];
                    acc[2*j]   = ffma2(vv, w.x, acc[2*j]);
                    acc[2*j+1] = ffma2(vv, w.y, acc[2*j+1]);
                }
            }
        }
    }

    size_t pix = (size_t)oy * W2 + ox;
#pragma unroll
    for (int j = 0; j < 16; j++) {
        float a0, a1;
        unpack2(acc[j], a0, a1);
        int oc = half * 32 + 2 * j;
        h1[((size_t)b * CD + oc)     * P2 + pix] = fmaxf(a0 + __ldg(bd + oc),     0.f);
        h1[((size_t)b * CD + oc + 1) * P2 + pix] = fmaxf(a1 + __ldg(bd + oc + 1), 0.f);
    }
}

// ---------------------------------------------------------------------------
// Kernel D: convT1 (64->32, 4x4, s2, p1) + bias + relu. (unchanged)
// ---------------------------------------------------------------------------
__global__ void __launch_bounds__(128)
k_convT1(const float* __restrict__ h1,
         const float* __restrict__ wt1,
         const float* __restrict__ bt1,
         float* __restrict__ h2)
{
    __shared__ __align__(16) float ws[4 * 64 * 32];
    int q  = blockIdx.y;
    int py = q >> 1, px = q & 1;
    int ky0 = py ? 0 : 1;
    int kx0 = px ? 0 : 1;
    for (int i = threadIdx.x; i < 8192; i += blockDim.x) {
        int oc = i & 31, ic = (i >> 5) & 63, comb = i >> 11;
        int dy = comb >> 1, dx = comb & 1;
        int ky = ky0 + 2 * dy, kx = kx0 + 2 * dx;
        ws[i] = wt1[(size_t)ic * 512 + (size_t)oc * 16 + ky * 4 + kx];
    }
    __syncthreads();

    int idx = blockIdx.x * blockDim.x + threadIdx.x;
    if (idx >= BATCH * (H3 / 2) * (W3 / 4)) return;
    int k   = idx % (W3 / 4);
    int tmp = idx / (W3 / 4);
    int oy2 = tmp % (H3 / 2);
    int b   = tmp / (H3 / 2);
    int oy   = 2 * oy2 + py;
    int ox_a = px + 4 * k;

    int Y = (oy + 1 - ky0) >> 1;
    int X = (ox_a + 1 - kx0) >> 1;

    u64 acc[2][16];
#pragma unroll
    for (int p = 0; p < 2; p++)
#pragma unroll
        for (int i = 0; i < 16; i++) acc[p][i] = 0ull;

    const float* hb = h1 + (size_t)b * CD * P2;

#pragma unroll
    for (int dy = 0; dy < 2; dy++) {
        int iy = Y - dy;
        if ((unsigned)iy >= (unsigned)H2) continue;
        const float* hr = hb + (size_t)iy * W2;
        for (int ic = 0; ic < 64; ic++) {
            const float* hp = hr + (size_t)ic * P2;
            float v[3];
#pragma unroll
            for (int j = 0; j < 3; j++) {
                int ix = X - 1 + j;
                v[j] = ((unsigned)ix < (unsigned)W2) ? __ldg(hp + ix) : 0.f;
            }
#pragma unroll
            for (int dx = 0; dx < 2; dx++) {
                u64 va = bcast2(v[1 - dx]);
                u64 vb = bcast2(v[2 - dx]);
                const ulonglong2* wp = (const ulonglong2*)(ws + ((dy * 2 + dx) * 64 + ic) * 32);
#pragma unroll
                for (int j = 0; j < 8; j++) {
                    ulonglong2 w = wp[j];
                    acc[0][2*j]   = ffma2(va, w.x, acc[0][2*j]);
                    acc[0][2*j+1] = ffma2(va, w.y, acc[0][2*j+1]);
                    acc[1][2*j]   = ffma2(vb, w.x, acc[1][2*j]);
                    acc[1][2*j+1] = ffma2(vb, w.y, acc[1][2*j+1]);
                }
            }
        }
    }

    size_t pixa = (size_t)oy * W3 + ox_a;
#pragma unroll
    for (int j = 0; j < 16; j++) {
        float a0, a1, b0, b1;
        unpack2(acc[0][j], a0, a1);
        unpack2(acc[1][j], b0, b1);
        int oc = 2 * j;
        float bias0 = __ldg(bt1 + oc), bias1 = __ldg(bt1 + oc + 1);
        size_t o0 = ((size_t)b * C2 + oc)     * (H3 * W3) + pixa;
        size_t o1 = ((size_t)b * C2 + oc + 1) * (H3 * W3) + pixa;
        h2[o0]     = fmaxf(a0 + bias0, 0.f);
        h2[o0 + 2] = fmaxf(b0 + bias0, 0.f);
        h2[o1]     = fmaxf(a1 + bias1, 0.f);
        h2[o1 + 2] = fmaxf(b1 + bias1, 0.f);
    }
}

// ---------------------------------------------------------------------------
// Kernel E: convT2 (32->2, 4x4, s2, p1) + bias + softplus. (unchanged)
// ---------------------------------------------------------------------------
__global__ void k_convT2(const float* __restrict__ h2,
                         const float* __restrict__ wt2,
                         const float* __restrict__ bt2,
                         float* __restrict__ out)
{
    __shared__ __align__(16) float ws[4 * 32 * 2];
    int q  = blockIdx.y;
    int py = q >> 1, px = q & 1;
    int ky0 = py ? 0 : 1;
    int kx0 = px ? 0 : 1;
    for (int i = threadIdx.x; i < 256; i += blockDim.x) {
        int oc = i & 1, ic = (i >> 1) & 31, comb = i >> 6;
        int dy = comb >> 1, dx = comb & 1;
        int ky = ky0 + 2 * dy, kx = kx0 + 2 * dx;
        ws[i] = wt2[(size_t)ic * 32 + oc * 16 + ky * 4 + kx];
    }
    __syncthreads();

    int idx = blockIdx.x * blockDim.x + threadIdx.x;
    if (idx >= BATCH * (H4 / 4) * (W4 / 4)) return;
    int k   = idx % (W4 / 4);
    int tmp = idx / (W4 / 4);
    int j2  = tmp % (H4 / 4);
    int b   = tmp / (H4 / 4);
    int oy_a = py + 4 * j2;
    int ox_a = px + 4 * k;

    int Y = (oy_a + 1 - ky0) >> 1;
    int X = (ox_a + 1 - kx0) >> 1;

    u64 acc[4];
    u64 binit = pack2(__ldg(bt2 + 0), __ldg(bt2 + 1));
#pragma unroll
    for (int i = 0; i < 4; i++) acc[i] = binit;

    const u64* wsp = (const u64*)ws;
    const float* hb = h2 + (size_t)b * C2 * (H3 * W3);

    for (int ic = 0; ic < 32; ic++) {
        const float* hc = hb + (size_t)ic * (H3 * W3);
        float v[3][3];
#pragma unroll
        for (int r = 0; r < 3; r++) {
            int iy = Y - 1 + r;
            bool rok = ((unsigned)iy < (unsigned)H3);
            const float* hr = hc + (size_t)iy * W3;
#pragma unroll
            for (int c = 0; c < 3; c++) {
                int ix = X - 1 + c;
                v[r][c] = (rok && (unsigned)ix < (unsigned)W3) ? __ldg(hr + ix) : 0.f;
            }
        }
#pragma unroll
        for (int dy = 0; dy < 2; dy++) {
#pragma unroll
            for (int dx = 0; dx < 2; dx++) {
                u64 w = wsp[(dy * 2 + dx) * 32 + ic];
#pragma unroll
                for (int yi = 0; yi < 2; yi++)
#pragma unroll
                    for (int xj = 0; xj < 2; xj++)
                        acc[yi * 2 + xj] = ffma2(bcast2(v[1 + yi - dy][1 + xj - dx]), w,
                                                 acc[yi * 2 + xj]);
            }
        }
    }

#pragma unroll
    for (int yi = 0; yi < 2; yi++) {
#pragma unroll
        for (int xj = 0; xj < 2; xj++) {
            float a0, a1;
            unpack2(acc[yi * 2 + xj], a0, a1);
            float o0 = fmaxf(a0, 0.f) + log1pf(expf(-fabsf(a0)));
            float o1 = fmaxf(a1, 0.f) + log1pf(expf(-fabsf(a1)));
            int oy = oy_a + 2 * yi, ox = ox_a + 2 * xj;
            size_t pix = (size_t)b * (H4 * W4) + (size_t)oy * W4 + ox;
            out[pix] = o0;
            out[(size_t)BATCH * H4 * W4 + pix] = o1;
        }
    }
}

// ---------------------------------------------------------------------------
// Launch
// ---------------------------------------------------------------------------
extern "C" void kernel_launch(void* const* d_in, const int* in_sizes, int n_in,
                              void* d_out, int out_size)
{
    (void)in_sizes; (void)n_in; (void)out_size;
    const float* x   = (const float*)d_in[0];
    const float* w1  = (const float*)d_in[1];
    const float* w2  = (const float*)d_in[2];
    const float* wd  = (const float*)d_in[3];
    const float* bd  = (const float*)d_in[4];
    const float* wt1 = (const float*)d_in[5];
    const float* bt1 = (const float*)d_in[6];
    const float* wt2 = (const float*)d_in[7];
    const float* bt2 = (const float*)d_in[8];
    float* out = (float*)d_out;

    unsigned char *px8, *ps1;
    float *pm1, *pm2, *pm2T, *ph1, *ph2;
    cudaGetSymbolAddress((void**)&px8,  g_x8);
    cudaGetSymbolAddress((void**)&pm1,  g_m1);
    cudaGetSymbolAddress((void**)&ps1,  g_s1);
    cudaGetSymbolAddress((void**)&pm2,  g_m2);
    cudaGetSymbolAddress((void**)&pm2T, g_m2T);
    cudaGetSymbolAddress((void**)&ph1,  g_h1);
    cudaGetSymbolAddress((void**)&ph2,  g_h2);

    cudaMemsetAsync(pm1, 0, (size_t)M1_N * sizeof(float), 0);
    cudaMemsetAsync(pm2, 0, (size_t)M2_N * sizeof(float), 0);

    // x -> [t][p0][b] uint8
    k_transpose_x2<<<dim3(P0 / 32, T_STEPS), dim3(32, 8)>>>(x, px8);

    for (int t = 0; t < T_STEPS; t++) {
        k_conv1_lif<<<575, 256>>>(px8, w1, pm1, ps1, t);
        k_conv2_lif<<<575, 256>>>(ps1, w2, pm2);
    }

    // m2 -> [b][oc][p2] for the (unchanged) decoder
    k_transpose_m2<<<(C2 * P2) / 32, dim3(32, 8)>>>(pm2, pm2T);

    const int nC = BATCH * P2;                     // 73600
    const int nD = BATCH * (H3 / 2) * (W3 / 4);    // 36800 per parity combo
    const int nE = BATCH * (H4 / 4) * (W4 / 4);    // 73600 per parity combo

    k_convd <<<dim3((nC + 127) / 128, 2), 128>>>(pm2T, wd, bd, ph1);
    k_convT1<<<dim3((nD + 127) / 128, 4), 128>>>(ph1, wt1, bt1, ph2);
    k_convT2<<<dim3((nE + 127) / 128, 4), 128>>>(ph2, wt2, bt2, out);
}

// round 7
// speedup vs baseline: 1.5484x; 1.3374x over previous
#include <cuda_runtime.h>
#include <cuda_bf16.h>
#include <math.h>

// ---------------------------------------------------------------------------
// SNN_CNN_Hybrid — fused time-loop: LIF state lives in registers across all
// 16 steps. 2 launches for the whole recurrence. Batch on lanes, spikes as
// uint8, f32x2 FMA. Time loops kept ROLLED (#pragma unroll 1) to bound SASS
// size / ptxas time.
// ---------------------------------------------------------------------------

#define T_STEPS 16
#define BATCH   32
#define H0 100
#define W0 368
#define P0 (H0*W0)            // 36800
#define C1 16
#define H1 50
#define W1 184
#define P1 (H1*W1)            // 9200
#define C2 32
#define H2 25
#define W2 92
#define P2 (H2*W2)            // 2300
#define CD 64
#define H3 50
#define W3 184
#define H4 100
#define W4 368

#define M2_N (C2*P2*BATCH)
#define H1_N (BATCH*CD*P2)
#define H2_N (BATCH*C2*H3*W3)

// Persistent scratch (static device globals; no runtime allocation)
__device__ unsigned char g_x8[(size_t)T_STEPS*P0*BATCH];     // [t][p0][b] binary
__device__ unsigned char g_s1[(size_t)T_STEPS*C1*P1*BATCH];  // [t][ic][p1][b] binary
__device__ float         g_m2[M2_N];                         // [oc][p2][b]
__device__ float         g_m2T[M2_N];                        // [b][oc][p2]
__device__ float         g_h1[H1_N];
__device__ float         g_h2[H2_N];

typedef unsigned long long u64;

__device__ __forceinline__ u64 pack2(float a, float b) {
    u64 r;
    asm("mov.b64 %0, {%1, %2};" : "=l"(r) : "f"(a), "f"(b));
    return r;
}
__device__ __forceinline__ u64 bcast2(float a) { return pack2(a, a); }
__device__ __forceinline__ void unpack2(u64 v, float& a, float& b) {
    asm("mov.b64 {%0, %1}, %2;" : "=f"(a), "=f"(b) : "l"(v));
}
__device__ __forceinline__ u64 ffma2(u64 a, u64 b, u64 c) {
    u64 d;
    asm("fma.rn.f32x2 %0, %1, %2, %3;" : "=l"(d) : "l"(a), "l"(b), "l"(c));
    return d;
}

// ---------------------------------------------------------------------------
// Transpose x: [t][b][p0] float -> [t][p0][b] uint8 (values exactly 0/1).
// ---------------------------------------------------------------------------
__global__ void k_transpose_x2(const float* __restrict__ x,
                               unsigned char* __restrict__ x8)
{
    __shared__ float tile[32][33];   // [b][p_local]
    int t  = blockIdx.y;
    int p0 = blockIdx.x * 32;
    int tx = threadIdx.x;
#pragma unroll
    for (int yy = 0; yy < 4; yy++) {
        int b = threadIdx.y + yy * 8;
        tile[b][tx] = x[((size_t)(t * BATCH + b)) * P0 + p0 + tx];   // coalesced over p
    }
    __syncthreads();
#pragma unroll
    for (int yy = 0; yy < 4; yy++) {
        int pl = threadIdx.y + yy * 8;
        x8[((size_t)t * P0 + p0 + pl) * BATCH + tx] = (unsigned char)tile[tx][pl];
    }
}

// ---------------------------------------------------------------------------
// Transpose m2: [oc][p2][b] -> [b][oc][p2]
// ---------------------------------------------------------------------------
__global__ void k_transpose_m2(const float* __restrict__ m2,
                               float* __restrict__ m2T)
{
    __shared__ float tile[32][33];
    const int R = C2 * P2;
    int r0 = blockIdx.x * 32;
    int tx = threadIdx.x;
#pragma unroll
    for (int yy = 0; yy < 4; yy++) {
        int rl = threadIdx.y + yy * 8;
        tile[rl][tx] = m2[(size_t)(r0 + rl) * BATCH + tx];
    }
    __syncthreads();
#pragma unroll
    for (int yy = 0; yy < 4; yy++) {
        int b = threadIdx.y + yy * 8;
        m2T[(size_t)b * R + r0 + tx] = tile[tx][b];
    }
}

// ---------------------------------------------------------------------------
// kF1: full 16-step conv1(1->16,5x5,s2,p2)+LIF recurrence in ONE launch.
// Warp = (oy, pair of adjacent ox); lane = b. m1 in registers across t.
// ---------------------------------------------------------------------------
__global__ void __launch_bounds__(256)
kF1(const unsigned char* __restrict__ x8,
    const float* __restrict__ w1,
    unsigned char* __restrict__ s1)
{
    __shared__ __align__(16) float ws[25 * 16];   // [tap][oc]
    for (int i = threadIdx.x; i < 400; i += 256) {
        int oc = i & 15, tap = i >> 4;
        ws[i] = w1[oc * 25 + tap];
    }
    __syncthreads();

    int wg   = blockIdx.x * 8 + (threadIdx.x >> 5);   // 0..4599
    int lane = threadIdx.x & 31;
    int xp = wg % (W1 / 2);          // 0..91
    int oy = wg / (W1 / 2);          // 0..49
    int p1 = oy * W1 + 2 * xp;

    const u64 c05 = bcast2(0.5f);

    u64 m[2][8];                     // m1 state: [pixel][oc-pair], regs only
#pragma unroll
    for (int p = 0; p < 2; p++)
#pragma unroll
        for (int i = 0; i < 8; i++) m[p][i] = 0ull;

#pragma unroll 1
    for (int t = 0; t < T_STEPS; t++) {
        u64 acc[2][8];
#pragma unroll
        for (int p = 0; p < 2; p++)
#pragma unroll
            for (int i = 0; i < 8; i++) acc[p][i] = 0ull;

        const unsigned char* xb = x8 + (size_t)t * P0 * BATCH;

#pragma unroll
        for (int ky = 0; ky < 5; ky++) {
            int iy = oy * 2 - 2 + ky;
            if ((unsigned)iy >= (unsigned)H0) continue;
            const unsigned char* xr = xb + (size_t)iy * W0 * BATCH;
            float v[7];
#pragma unroll
            for (int j = 0; j < 7; j++) {
                int ix = 4 * xp - 2 + j;
                v[j] = ((unsigned)ix < (unsigned)W0)
                     ? (float)xr[(size_t)ix * BATCH + lane] : 0.f;
            }
#pragma unroll
            for (int kx = 0; kx < 5; kx++) {
                u64 vv0 = bcast2(v[kx]);
                u64 vv1 = bcast2(v[kx + 2]);
                const ulonglong2* wp = (const ulonglong2*)(ws + (ky * 5 + kx) * 16);
#pragma unroll
                for (int j = 0; j < 4; j++) {
                    ulonglong2 w = wp[j];
                    acc[0][2*j]   = ffma2(vv0, w.x, acc[0][2*j]);
                    acc[0][2*j+1] = ffma2(vv0, w.y, acc[0][2*j+1]);
                    acc[1][2*j]   = ffma2(vv1, w.x, acc[1][2*j]);
                    acc[1][2*j+1] = ffma2(vv1, w.y, acc[1][2*j+1]);
                }
            }
        }

        unsigned char* so = s1 + (size_t)t * C1 * P1 * BATCH;
#pragma unroll
        for (int j = 0; j < 8; j++) {
#pragma unroll
            for (int p = 0; p < 2; p++) {
                m[p][j] = ffma2(m[p][j], c05, acc[p][j]);   // m*0.5 + conv
                float a0, a1;
                unpack2(m[p][j], a0, a1);
                bool sp0 = (a0 >= 1.0f);
                bool sp1 = (a1 >= 1.0f);
                if (sp0) a0 = 0.f;
                if (sp1) a1 = 0.f;
                m[p][j] = pack2(a0, a1);
                so[((size_t)(2*j)   * P1 + p1 + p) * BATCH + lane] = sp0 ? 1 : 0;
                so[((size_t)(2*j+1) * P1 + p1 + p) * BATCH + lane] = sp1 ? 1 : 0;
            }
        }
    }
}

// ---------------------------------------------------------------------------
// kF2: full 16-step conv2(16->32,3x3,s2,p1)+LIF recurrence in ONE launch.
// Warp = one output pixel, all 32 oc; lane = b. m2 in registers across t.
// Ballot skip of all-zero spike rows.
// ---------------------------------------------------------------------------
__global__ void __launch_bounds__(256)
kF2(const unsigned char* __restrict__ s1,
    const float* __restrict__ w2,
    float* __restrict__ m2out)
{
    __shared__ __align__(16) float ws[144 * 32];   // [(ic*9+kk)][oc]
    for (int i = threadIdx.x; i < 4608; i += 256) {
        int oc = i & 31, r = i >> 5;
        ws[i] = w2[oc * 144 + r];
    }
    __syncthreads();

    int wg   = blockIdx.x * 8 + (threadIdx.x >> 5);   // 0..2303
    int lane = threadIdx.x & 31;
    if (wg >= P2) return;
    int ox = wg % W2;                 // 0..91
    int oy = wg / W2;                 // 0..24

    const u64 c05 = bcast2(0.5f);

    u64 m[16];                        // m2 state: oc-pairs, regs only
#pragma unroll
    for (int i = 0; i < 16; i++) m[i] = 0ull;

#pragma unroll 1
    for (int t = 0; t < T_STEPS; t++) {
        u64 acc[16];
#pragma unroll
        for (int i = 0; i < 16; i++) acc[i] = 0ull;

        const unsigned char* sb = s1 + (size_t)t * C1 * P1 * BATCH;

#pragma unroll 1
        for (int ic = 0; ic < 16; ic++) {
            const unsigned char* sc = sb + (size_t)ic * P1 * BATCH;
#pragma unroll
            for (int ky = 0; ky < 3; ky++) {
                int iy = oy * 2 - 1 + ky;
                if ((unsigned)iy >= (unsigned)H1) continue;
                const unsigned char* sr = sc + (size_t)iy * W1 * BATCH;
                float v[3];
#pragma unroll
                for (int j = 0; j < 3; j++) {
                    int ix = 2 * ox - 1 + j;
                    v[j] = ((unsigned)ix < (unsigned)W1)
                         ? (float)sr[(size_t)ix * BATCH + lane] : 0.f;
                }
                // spikes are sparse: skip whole row if no lane has any spike
                if (!__ballot_sync(0xFFFFFFFFu, (v[0] + v[1] + v[2]) != 0.f))
                    continue;
#pragma unroll
                for (int kx = 0; kx < 3; kx++) {
                    u64 vv = bcast2(v[kx]);
                    const ulonglong2* wp =
                        (const ulonglong2*)(ws + (ic * 9 + ky * 3 + kx) * 32);
#pragma unroll
                    for (int j = 0; j < 8; j++) {
                        ulonglong2 w = wp[j];
                        acc[2*j]   = ffma2(vv, w.x, acc[2*j]);
                        acc[2*j+1] = ffma2(vv, w.y, acc[2*j+1]);
                    }
                }
            }
        }

#pragma unroll
        for (int j = 0; j < 16; j++) {
            m[j] = ffma2(m[j], c05, acc[j]);
            float a0, a1;
            unpack2(m[j], a0, a1);
            if (a0 >= 1.0f) a0 = 0.f;
            if (a1 >= 1.0f) a1 = 0.f;
            m[j] = pack2(a0, a1);
        }
    }

    int p2 = oy * W2 + ox;
#pragma unroll
    for (int j = 0; j < 16; j++) {
        float a0, a1;
        unpack2(m[j], a0, a1);
        m2out[((size_t)(2*j)   * P2 + p2) * BATCH + lane] = a0;
        m2out[((size_t)(2*j+1) * P2 + p2) * BATCH + lane] = a1;
    }
}

// ---------------------------------------------------------------------------
// Kernel C: decoder conv (32->64, 3x3, s1, p1) + bias + relu.
// ---------------------------------------------------------------------------
__global__ void k_convd(const float* __restrict__ m2,
                        const float* __restrict__ wd,
                        const float* __restrict__ bd,
                        float* __restrict__ h1)
{
    __shared__ __align__(16) float ws[288 * 32];
    int half = blockIdx.y;
    for (int i = threadIdx.x; i < 9216; i += blockDim.x) {
        int ol = i & 31, r = i >> 5;
        ws[i] = wd[(size_t)(half * 32 + ol) * 288 + r];
    }
    __syncthreads();

    int idx = blockIdx.x * blockDim.x + threadIdx.x;
    if (idx >= BATCH * P2) return;
    int ox = idx % W2;
    int tmp = idx / W2;
    int oy = tmp % H2;
    int b  = tmp / H2;

    u64 acc[16];
#pragma unroll
    for (int i = 0; i < 16; i++) acc[i] = 0ull;

    const float* xb = m2 + (size_t)b * C2 * P2;

#pragma unroll 1
    for (int ic = 0; ic < 32; ic++) {
        const float* xc = xb + (size_t)ic * P2;
#pragma unroll
        for (int ky = 0; ky < 3; ky++) {
            int iy = oy - 1 + ky;
            if ((unsigned)iy >= (unsigned)H2) continue;
            const float* xr = xc + iy * W2;
#pragma unroll
            for (int kx = 0; kx < 3; kx++) {
                int ix = ox - 1 + kx;
                if ((unsigned)ix >= (unsigned)W2) continue;
                u64 vv = bcast2(__ldg(xr + ix));
                const ulonglong2* wp = (const ulonglong2*)(ws + (ic * 9 + ky * 3 + kx) * 32);
#pragma unroll
                for (int j = 0; j < 8; j++) {
                    ulonglong2 w = wp[j];
                    acc[2*j]   = ffma2(vv, w.x, acc[2*j]);
                    acc[2*j+1] = ffma2(vv, w.y, acc[2*j+1]);
                }
            }
        }
    }

    size_t pix = (size_t)oy * W2 + ox;
#pragma unroll
    for (int j = 0; j < 16; j++) {
        float a0, a1;
        unpack2(acc[j], a0, a1);
        int oc = half * 32 + 2 * j;
        h1[((size_t)b * CD + oc)     * P2 + pix] = fmaxf(a0 + __ldg(bd + oc),     0.f);
        h1[((size_t)b * CD + oc + 1) * P2 + pix] = fmaxf(a1 + __ldg(bd + oc + 1), 0.f);
    }
}

// ---------------------------------------------------------------------------
// Kernel D: convT1 (64->32, 4x4, s2, p1) + bias + relu.
// ---------------------------------------------------------------------------
__global__ void __launch_bounds__(128)
k_convT1(const float* __restrict__ h1,
         const float* __restrict__ wt1,
         const float* __restrict__ bt1,
         float* __restrict__ h2)
{
    __shared__ __align__(16) float ws[4 * 64 * 32];
    int q  = blockIdx.y;
    int py = q >> 1, px = q & 1;
    int ky0 = py ? 0 : 1;
    int kx0 = px ? 0 : 1;
    for (int i = threadIdx.x; i < 8192; i += blockDim.x) {
        int oc = i & 31, ic = (i >> 5) & 63, comb = i >> 11;
        int dy = comb >> 1, dx = comb & 1;
        int ky = ky0 + 2 * dy, kx = kx0 + 2 * dx;
        ws[i] = wt1[(size_t)ic * 512 + (size_t)oc * 16 + ky * 4 + kx];
    }
    __syncthreads();

    int idx = blockIdx.x * blockDim.x + threadIdx.x;
    if (idx >= BATCH * (H3 / 2) * (W3 / 4)) return;
    int k   = idx % (W3 / 4);
    int tmp = idx / (W3 / 4);
    int oy2 = tmp % (H3 / 2);
    int b   = tmp / (H3 / 2);
    int oy   = 2 * oy2 + py;
    int ox_a = px + 4 * k;

    int Y = (oy + 1 - ky0) >> 1;
    int X = (ox_a + 1 - kx0) >> 1;

    u64 acc[2][16];
#pragma unroll
    for (int p = 0; p < 2; p++)
#pragma unroll
        for (int i = 0; i < 16; i++) acc[p][i] = 0ull;

    const float* hb = h1 + (size_t)b * CD * P2;

#pragma unroll
    for (int dy = 0; dy < 2; dy++) {
        int iy = Y - dy;
        if ((unsigned)iy >= (unsigned)H2) continue;
        const float* hr = hb + (size_t)iy * W2;
#pragma unroll 1
        for (int ic = 0; ic < 64; ic++) {
            const float* hp = hr + (size_t)ic * P2;
            float v[3];
#pragma unroll
            for (int j = 0; j < 3; j++) {
                int ix = X - 1 + j;
                v[j] = ((unsigned)ix < (unsigned)W2) ? __ldg(hp + ix) : 0.f;
            }
#pragma unroll
            for (int dx = 0; dx < 2; dx++) {
                u64 va = bcast2(v[1 - dx]);
                u64 vb = bcast2(v[2 - dx]);
                const ulonglong2* wp = (const ulonglong2*)(ws + ((dy * 2 + dx) * 64 + ic) * 32);
#pragma unroll
                for (int j = 0; j < 8; j++) {
                    ulonglong2 w = wp[j];
                    acc[0][2*j]   = ffma2(va, w.x, acc[0][2*j]);
                    acc[0][2*j+1] = ffma2(va, w.y, acc[0][2*j+1]);
                    acc[1][2*j]   = ffma2(vb, w.x, acc[1][2*j]);
                    acc[1][2*j+1] = ffma2(vb, w.y, acc[1][2*j+1]);
                }
            }
        }
    }

    size_t pixa = (size_t)oy * W3 + ox_a;
#pragma unroll
    for (int j = 0; j < 16; j++) {
        float a0, a1, b0, b1;
        unpack2(acc[0][j], a0, a1);
        unpack2(acc[1][j], b0, b1);
        int oc = 2 * j;
        float bias0 = __ldg(bt1 + oc), bias1 = __ldg(bt1 + oc + 1);
        size_t o0 = ((size_t)b * C2 + oc)     * (H3 * W3) + pixa;
        size_t o1 = ((size_t)b * C2 + oc + 1) * (H3 * W3) + pixa;
        h2[o0]     = fmaxf(a0 + bias0, 0.f);
        h2[o0 + 2] = fmaxf(b0 + bias0, 0.f);
        h2[o1]     = fmaxf(a1 + bias1, 0.f);
        h2[o1 + 2] = fmaxf(b1 + bias1, 0.f);
    }
}

// ---------------------------------------------------------------------------
// Kernel E: convT2 (32->2, 4x4, s2, p1) + bias + softplus.
// ---------------------------------------------------------------------------
__global__ void k_convT2(const float* __restrict__ h2,
                         const float* __restrict__ wt2,
                         const float* __restrict__ bt2,
                         float* __restrict__ out)
{
    __shared__ __align__(16) float ws[4 * 32 * 2];
    int q  = blockIdx.y;
    int py = q >> 1, px = q & 1;
    int ky0 = py ? 0 : 1;
    int kx0 = px ? 0 : 1;
    for (int i = threadIdx.x; i < 256; i += blockDim.x) {
        int oc = i & 1, ic = (i >> 1) & 31, comb = i >> 6;
        int dy = comb >> 1, dx = comb & 1;
        int ky = ky0 + 2 * dy, kx = kx0 + 2 * dx;
        ws[i] = wt2[(size_t)ic * 32 + oc * 16 + ky * 4 + kx];
    }
    __syncthreads();

    int idx = blockIdx.x * blockDim.x + threadIdx.x;
    if (idx >= BATCH * (H4 / 4) * (W4 / 4)) return;
    int k   = idx % (W4 / 4);
    int tmp = idx / (W4 / 4);
    int j2  = tmp % (H4 / 4);
    int b   = tmp / (H4 / 4);
    int oy_a = py + 4 * j2;
    int ox_a = px + 4 * k;

    int Y = (oy_a + 1 - ky0) >> 1;
    int X = (ox_a + 1 - kx0) >> 1;

    u64 acc[4];
    u64 binit = pack2(__ldg(bt2 + 0), __ldg(bt2 + 1));
#pragma unroll
    for (int i = 0; i < 4; i++) acc[i] = binit;

    const u64* wsp = (const u64*)ws;
    const float* hb = h2 + (size_t)b * C2 * (H3 * W3);

#pragma unroll 1
    for (int ic = 0; ic < 32; ic++) {
        const float* hc = hb + (size_t)ic * (H3 * W3);
        float v[3][3];
#pragma unroll
        for (int r = 0; r < 3; r++) {
            int iy = Y - 1 + r;
            bool rok = ((unsigned)iy < (unsigned)H3);
            const float* hr = hc + (size_t)iy * W3;
#pragma unroll
            for (int c = 0; c < 3; c++) {
                int ix = X - 1 + c;
                v[r][c] = (rok && (unsigned)ix < (unsigned)W3) ? __ldg(hr + ix) : 0.f;
            }
        }
#pragma unroll
        for (int dy = 0; dy < 2; dy++) {
#pragma unroll
            for (int dx = 0; dx < 2; dx++) {
                u64 w = wsp[(dy * 2 + dx) * 32 + ic];
#pragma unroll
                for (int yi = 0; yi < 2; yi++)
#pragma unroll
                    for (int xj = 0; xj < 2; xj++)
                        acc[yi * 2 + xj] = ffma2(bcast2(v[1 + yi - dy][1 + xj - dx]), w,
                                                 acc[yi * 2 + xj]);
            }
        }
    }

#pragma unroll
    for (int yi = 0; yi < 2; yi++) {
#pragma unroll
        for (int xj = 0; xj < 2; xj++) {
            float a0, a1;
            unpack2(acc[yi * 2 + xj], a0, a1);
            float o0 = fmaxf(a0, 0.f) + log1pf(expf(-fabsf(a0)));
            float o1 = fmaxf(a1, 0.f) + log1pf(expf(-fabsf(a1)));
            int oy = oy_a + 2 * yi, ox = ox_a + 2 * xj;
            size_t pix = (size_t)b * (H4 * W4) + (size_t)oy * W4 + ox;
            out[pix] = o0;
            out[(size_t)BATCH * H4 * W4 + pix] = o1;
        }
    }
}

// ---------------------------------------------------------------------------
// Launch
// ---------------------------------------------------------------------------
extern "C" void kernel_launch(void* const* d_in, const int* in_sizes, int n_in,
                              void* d_out, int out_size)
{
    (void)in_sizes; (void)n_in; (void)out_size;
    const float* x   = (const float*)d_in[0];
    const float* w1  = (const float*)d_in[1];
    const float* w2  = (const float*)d_in[2];
    const float* wd  = (const float*)d_in[3];
    const float* bd  = (const float*)d_in[4];
    const float* wt1 = (const float*)d_in[5];
    const float* bt1 = (const float*)d_in[6];
    const float* wt2 = (const float*)d_in[7];
    const float* bt2 = (const float*)d_in[8];
    float* out = (float*)d_out;

    unsigned char *px8, *ps1;
    float *pm2, *pm2T, *ph1, *ph2;
    cudaGetSymbolAddress((void**)&px8,  g_x8);
    cudaGetSymbolAddress((void**)&ps1,  g_s1);
    cudaGetSymbolAddress((void**)&pm2,  g_m2);
    cudaGetSymbolAddress((void**)&pm2T, g_m2T);
    cudaGetSymbolAddress((void**)&ph1,  g_h1);
    cudaGetSymbolAddress((void**)&ph2,  g_h2);

    // x -> [t][p0][b] uint8
    k_transpose_x2<<<dim3(P0 / 32, T_STEPS), dim3(32, 8)>>>(x, px8);

    // full conv1+LIF recurrence (state in regs), writes s1(t) for all t
    kF1<<<575, 256>>>(px8, w1, ps1);

    // full conv2+LIF recurrence (state in regs), writes final m2
    kF2<<<(P2 + 7) / 8, 256>>>(ps1, w2, pm2);

    // m2 -> [b][oc][p2] for the decoder
    k_transpose_m2<<<(C2 * P2) / 32, dim3(32, 8)>>>(pm2, pm2T);

    const int nC = BATCH * P2;
    const int nD = BATCH * (H3 / 2) * (W3 / 4);
    const int nE = BATCH * (H4 / 4) * (W4 / 4);

    k_convd <<<dim3((nC + 127) / 128, 2), 128>>>(pm2T, wd, bd, ph1);
    k_convT1<<<dim3((nD + 127) / 128, 4), 128>>>(ph1, wt1, bt1, ph2);
    k_convT2<<<dim3((nE + 127) / 128, 4), 128>>>(ph2, wt2, bt2, out);
}